// round 16
// baseline (speedup 1.0000x reference)
#include <cuda_runtime.h>
#include <math.h>

#define TILE 16    // node kernels
#define TE 32      // edge kernels (two 16-row MMA tiles)
#define NTHREADS 128
#define NMAX 50000
#define EMAX 600000
#define LDH 136   // padded smem row stride for node kernels
#define LDO 264   // padded stride for 256-wide input tiles
#define LDE 40    // padded stride for 32-wide edge-feature tiles
#define PST 66    // uint2 stride for packed hidden state (64 pairs + pad)

// packed bf16 fragment arrays, offsets in uint4 units
#define P_QW1  0
#define P_QW2  4096
#define P_KW1D 8192
#define P_KW1S 12288
#define P_VW1D 16384
#define P_VW1S 20480
#define P_KW2  24576
#define P_VW2  28672
#define P_OW1  32768
#define P_OW2  40960
#define P_KW1A 45056   // kW1[0:24] zero-padded to K=32
#define P_VW1A 46080   // vW1[0:24] zero-padded to K=32
#define P_TOTAL 47104

// ---------------- device scratch (no allocations allowed) ----------------
__device__ float g_q[NMAX * 128];
__device__ float g_kHd[NMAX * 128];
__device__ float g_kHs[NMAX * 128];
__device__ float g_vHd[NMAX * 128];
__device__ float g_vHs[NMAX * 128];
__device__ float g_attn[NMAX * 128];
__device__ float g_mx[NMAX * 16];
__device__ float g_den[NMAX * 16];
__device__ float g_scores[EMAX * 16];
__device__ uint4 g_wpk[P_TOTAL];

// ---------------- bf16 helpers ----------------
__device__ __forceinline__ unsigned pk_bf16x2(float lo, float hi) {
    unsigned r;
    asm("cvt.rn.bf16x2.f32 %0, %1, %2;" : "=r"(r) : "f"(hi), "f"(lo));
    return r;
}
__device__ __forceinline__ unsigned pk_residual(float2 x, unsigned h) {
    const float hlo = __uint_as_float(h << 16);
    const float hhi = __uint_as_float(h & 0xFFFF0000u);
    return pk_bf16x2(x.x - hlo, x.y - hhi);
}

__device__ __forceinline__ void mma16(float (&c)[4], unsigned a0, unsigned a1,
                                      unsigned a2, unsigned a3,
                                      unsigned b0, unsigned b1) {
    asm("mma.sync.aligned.m16n8k16.row.col.f32.bf16.bf16.f32 "
        "{%0,%1,%2,%3}, {%4,%5,%6,%7}, {%8,%9}, {%0,%1,%2,%3};"
        : "+f"(c[0]), "+f"(c[1]), "+f"(c[2]), "+f"(c[3])
        : "r"(a0), "r"(a1), "r"(a2), "r"(a3), "r"(b0), "r"(b1));
}

// vector reduction: g_attn[ptr..ptr+1] += {x, y}  (sm_90+)
__device__ __forceinline__ void red_add_v2(float* ptr, float x, float y) {
    asm volatile("red.global.add.v2.f32 [%0], {%1, %2};"
                 :: "l"(ptr), "f"(x), "f"(y) : "memory");
}

// monotone float atomic max via signed/unsigned int tricks (init to -inf)
__device__ __forceinline__ void atomicMaxF(float* addr, float v) {
    if (v >= 0.f) atomicMax((int*)addr, __float_as_int(v));
    else          atomicMin((unsigned int*)addr, __float_as_uint(v));
}

// ---------------- A-fragment pack from fp32 smem ----------------
struct AFrag { unsigned ah0, ah1, ah2, ah3, al0, al1, al2, al3; };

template <int LDA>
__device__ __forceinline__ AFrag load_afrag(const float* __restrict__ A_s, int k,
                                            int g, int tig) {
    const float2 p0 = *(const float2*)(A_s + g * LDA + k + 2 * tig);
    const float2 p1 = *(const float2*)(A_s + (g + 8) * LDA + k + 2 * tig);
    const float2 p2 = *(const float2*)(A_s + g * LDA + k + 8 + 2 * tig);
    const float2 p3 = *(const float2*)(A_s + (g + 8) * LDA + k + 8 + 2 * tig);
    AFrag f;
    f.ah0 = pk_bf16x2(p0.x, p0.y); f.al0 = pk_residual(p0, f.ah0);
    f.ah1 = pk_bf16x2(p1.x, p1.y); f.al1 = pk_residual(p1, f.ah1);
    f.ah2 = pk_bf16x2(p2.x, p2.y); f.al2 = pk_residual(p2, f.ah2);
    f.ah3 = pk_bf16x2(p3.x, p3.y); f.al3 = pk_residual(p3, f.ah3);
    return f;
}

// A-fragment from pre-packed {hi,lo} uint2 smem (no conversions)
__device__ __forceinline__ AFrag load_apk(const uint2* __restrict__ pk,
                                          int row0, int kp, int tig) {
    const uint2 q0 = pk[row0 * PST + kp + tig];
    const uint2 q1 = pk[(row0 + 8) * PST + kp + tig];
    const uint2 q2 = pk[row0 * PST + kp + 4 + tig];
    const uint2 q3 = pk[(row0 + 8) * PST + kp + 4 + tig];
    AFrag f;
    f.ah0 = q0.x; f.al0 = q0.y;
    f.ah1 = q1.x; f.al1 = q1.y;
    f.ah2 = q2.x; f.al2 = q2.y;
    f.ah3 = q3.x; f.al3 = q3.y;
    return f;
}

__device__ __forceinline__ void mma3(float (&c)[4], const AFrag& f, const uint4& b) {
    mma16(c, f.ah0, f.ah1, f.ah2, f.ah3, b.x, b.y);
    mma16(c, f.al0, f.al1, f.al2, f.al3, b.x, b.y);
    mma16(c, f.ah0, f.ah1, f.ah2, f.ah3, b.z, b.w);
}

// ---------------- single-tile MMA core (node kernels) ----------------
template <int KIN, int LDA, bool BIAS>
__device__ __forceinline__ void mma_core(
    const float* __restrict__ A_s, const uint4* __restrict__ Bpk,
    const float* __restrict__ bias, float (&c)[4][4])
{
    const int lane = threadIdx.x & 31;
    const int warp = threadIdx.x >> 5;
    const int g = lane >> 2, tig = lane & 3;
    const int n0 = warp * 32;
#pragma unroll
    for (int nt = 0; nt < 4; nt++) {
        float be = 0.f, bo = 0.f;
        if (BIAS) {
            be = bias[n0 + nt * 8 + 2 * tig];
            bo = bias[n0 + nt * 8 + 2 * tig + 1];
        }
        c[nt][0] = be; c[nt][1] = bo; c[nt][2] = be; c[nt][3] = bo;
    }
#pragma unroll
    for (int k = 0; k < KIN; k += 16) {
        const AFrag f = load_afrag<LDA>(A_s, k, g, tig);
        const int kbase = (k >> 4) * 128;
#pragma unroll
        for (int nt = 0; nt < 4; nt++) {
            const int nc = n0 + nt * 8 + g;
            const uint4 b = Bpk[(kbase + nc) * 4 + tig];
            mma3(c[nt], f, b);
        }
    }
}

// dual-tile lin2 from packed hidden state: B loaded once, zero A conversions
template <bool BIAS>
__device__ __forceinline__ void mma_core_dual_pk(
    const uint2* __restrict__ pk_s, const uint4* __restrict__ Bpk,
    const float* __restrict__ bias, float (&c0)[4][4], float (&c1)[4][4])
{
    const int lane = threadIdx.x & 31;
    const int warp = threadIdx.x >> 5;
    const int g = lane >> 2, tig = lane & 3;
    const int n0 = warp * 32;
#pragma unroll
    for (int nt = 0; nt < 4; nt++) {
        float be = 0.f, bo = 0.f;
        if (BIAS) {
            be = bias[n0 + nt * 8 + 2 * tig];
            bo = bias[n0 + nt * 8 + 2 * tig + 1];
        }
        c0[nt][0] = be; c0[nt][1] = bo; c0[nt][2] = be; c0[nt][3] = bo;
        c1[nt][0] = be; c1[nt][1] = bo; c1[nt][2] = be; c1[nt][3] = bo;
    }
#pragma unroll
    for (int k = 0; k < 128; k += 16) {
        const int kp = k >> 1;
        const AFrag f0 = load_apk(pk_s, g, kp, tig);
        const AFrag f1 = load_apk(pk_s, 16 + g, kp, tig);
        const int kbase = (k >> 4) * 128;
#pragma unroll
        for (int nt = 0; nt < 4; nt++) {
            const int nc = n0 + nt * 8 + g;
            const uint4 b = Bpk[(kbase + nc) * 4 + tig];
            mma3(c0[nt], f0, b);
            mma3(c1[nt], f1, b);
        }
    }
}

// store fragments to smem (stride LDH) or global (row stride 128)
template <bool GLOBAL>
__device__ __forceinline__ void frag_store(float (&c)[4][4], float* __restrict__ C,
                                           int row0) {
    const int lane = threadIdx.x & 31;
    const int warp = threadIdx.x >> 5;
    const int g = lane >> 2, tig = lane & 3;
    const int n0 = warp * 32;
#pragma unroll
    for (int nt = 0; nt < 4; nt++) {
        const int ce = n0 + nt * 8 + 2 * tig;
        if (GLOBAL) {
            C[(row0 + g) * 128 + ce]     = c[nt][0];
            C[(row0 + g) * 128 + ce + 1] = c[nt][1];
            C[(row0 + g + 8) * 128 + ce]     = c[nt][2];
            C[(row0 + g + 8) * 128 + ce + 1] = c[nt][3];
        } else {
            C[(row0 + g) * LDH + ce]     = c[nt][0];
            C[(row0 + g) * LDH + ce + 1] = c[nt][1];
            C[(row0 + g + 8) * LDH + ce]     = c[nt][2];
            C[(row0 + g + 8) * LDH + ce + 1] = c[nt][3];
        }
    }
}

template <int KIN, int LDA, bool BIAS, bool GLOBAL>
__device__ __forceinline__ void mma_gemm16(
    const float* __restrict__ A_s, const uint4* __restrict__ Bpk,
    const float* __restrict__ bias, float* __restrict__ C, int row0)
{
    float c[4][4];
    mma_core<KIN, LDA, BIAS>(A_s, Bpk, bias, c);
    frag_store<GLOBAL>(c, C, row0);
}

// edge first layer (dual tile) -> fragments in registers
__device__ __forceinline__ void mma_edge_l1_dual(
    const float* __restrict__ A_s, const uint4* __restrict__ Bpk,
    const float* __restrict__ b1,
    const float* __restrict__ Hd, const float* __restrict__ Hs,
    const int* __restrict__ dst_s, const int* __restrict__ src_s,
    float (&c0)[4][4], float (&c1)[4][4])
{
    const int lane = threadIdx.x & 31;
    const int warp = threadIdx.x >> 5;
    const int g = lane >> 2, tig = lane & 3;
    const int n0 = warp * 32;
#pragma unroll
    for (int nt = 0; nt < 4; nt++) {
        const int ce = n0 + nt * 8 + 2 * tig;
        const float2 bd = *(const float2*)(b1 + ce);
        {
            const float2 d0 = *(const float2*)(Hd + dst_s[g] * 128 + ce);
            const float2 s0 = *(const float2*)(Hs + src_s[g] * 128 + ce);
            const float2 d8 = *(const float2*)(Hd + dst_s[g + 8] * 128 + ce);
            const float2 s8 = *(const float2*)(Hs + src_s[g + 8] * 128 + ce);
            c0[nt][0] = bd.x + d0.x + s0.x;
            c0[nt][1] = bd.y + d0.y + s0.y;
            c0[nt][2] = bd.x + d8.x + s8.x;
            c0[nt][3] = bd.y + d8.y + s8.y;
        }
        {
            const float2 d0 = *(const float2*)(Hd + dst_s[16 + g] * 128 + ce);
            const float2 s0 = *(const float2*)(Hs + src_s[16 + g] * 128 + ce);
            const float2 d8 = *(const float2*)(Hd + dst_s[24 + g] * 128 + ce);
            const float2 s8 = *(const float2*)(Hs + src_s[24 + g] * 128 + ce);
            c1[nt][0] = bd.x + d0.x + s0.x;
            c1[nt][1] = bd.y + d0.y + s0.y;
            c1[nt][2] = bd.x + d8.x + s8.x;
            c1[nt][3] = bd.y + d8.y + s8.y;
        }
    }
#pragma unroll
    for (int k = 0; k < 32; k += 16) {
        const AFrag f0 = load_afrag<LDE>(A_s, k, g, tig);
        const AFrag f1 = load_afrag<LDE>(A_s + 16 * LDE, k, g, tig);
        const int kbase = (k >> 4) * 128;
#pragma unroll
        for (int nt = 0; nt < 4; nt++) {
            const int nc = n0 + nt * 8 + g;
            const uint4 b = Bpk[(kbase + nc) * 4 + tig];
            mma3(c0[nt], f0, b);
            mma3(c1[nt], f1, b);
        }
    }
}

// fragment-resident LayerNorm + ReLU + bf16 pack into pk_s ({hi,lo} per col pair)
__device__ __forceinline__ void ln_frag_pack(
    float (&c0)[4][4], float (&c1)[4][4],
    float2* __restrict__ wsum,   // [32 rows][4 warps]
    uint2* __restrict__ pk_s,
    const float* __restrict__ gam, const float* __restrict__ bet)
{
    const int lane = threadIdx.x & 31;
    const int warp = threadIdx.x >> 5;
    const int g = lane >> 2, tig = lane & 3;
    const int n0 = warp * 32;

    // per-thread partial sums over its 8 cols for rows g, g+8, 16+g, 24+g
    float s[4] = {0.f, 0.f, 0.f, 0.f}, s2[4] = {0.f, 0.f, 0.f, 0.f};
#pragma unroll
    for (int nt = 0; nt < 4; nt++) {
        s[0] += c0[nt][0] + c0[nt][1];
        s2[0] += c0[nt][0] * c0[nt][0] + c0[nt][1] * c0[nt][1];
        s[1] += c0[nt][2] + c0[nt][3];
        s2[1] += c0[nt][2] * c0[nt][2] + c0[nt][3] * c0[nt][3];
        s[2] += c1[nt][0] + c1[nt][1];
        s2[2] += c1[nt][0] * c1[nt][0] + c1[nt][1] * c1[nt][1];
        s[3] += c1[nt][2] + c1[nt][3];
        s2[3] += c1[nt][2] * c1[nt][2] + c1[nt][3] * c1[nt][3];
    }
#pragma unroll
    for (int r = 0; r < 4; r++) {
        s[r]  += __shfl_xor_sync(0xffffffffu, s[r], 1);
        s[r]  += __shfl_xor_sync(0xffffffffu, s[r], 2);
        s2[r] += __shfl_xor_sync(0xffffffffu, s2[r], 1);
        s2[r] += __shfl_xor_sync(0xffffffffu, s2[r], 2);
    }
    if (tig == 0) {
        wsum[g * 4 + warp]        = make_float2(s[0], s2[0]);
        wsum[(g + 8) * 4 + warp]  = make_float2(s[1], s2[1]);
        wsum[(16 + g) * 4 + warp] = make_float2(s[2], s2[2]);
        wsum[(24 + g) * 4 + warp] = make_float2(s[3], s2[3]);
    }
    __syncthreads();

    const int rows[4] = {g, g + 8, 16 + g, 24 + g};
    float mu[4], rs[4];
#pragma unroll
    for (int r = 0; r < 4; r++) {
        float ts = 0.f, ts2 = 0.f;
#pragma unroll
        for (int w = 0; w < 4; w++) {
            const float2 v = wsum[rows[r] * 4 + w];
            ts += v.x; ts2 += v.y;
        }
        const float m = ts * (1.f / 128.f);
        mu[r] = m;
        rs[r] = rsqrtf(ts2 * (1.f / 128.f) - m * m + 1e-5f);
    }

    // normalize + affine + relu + pack {hi,lo}
#pragma unroll
    for (int nt = 0; nt < 4; nt++) {
        const int ce = n0 + nt * 8 + 2 * tig;
        const float2 gm = *(const float2*)(gam + ce);
        const float2 bt = *(const float2*)(bet + ce);
        const int pidx = (n0 >> 1) + nt * 4 + tig;
#pragma unroll
        for (int half = 0; half < 2; half++) {
            float (*cc)[4] = half ? c1 : c0;
            const int rA = half * 2, rB = half * 2 + 1;
            float2 vA, vB;
            vA.x = fmaxf(fmaf((cc[nt][0] - mu[rA]) * rs[rA], gm.x, bt.x), 0.f);
            vA.y = fmaxf(fmaf((cc[nt][1] - mu[rA]) * rs[rA], gm.y, bt.y), 0.f);
            vB.x = fmaxf(fmaf((cc[nt][2] - mu[rB]) * rs[rB], gm.x, bt.x), 0.f);
            vB.y = fmaxf(fmaf((cc[nt][3] - mu[rB]) * rs[rB], gm.y, bt.y), 0.f);
            uint2 pA, pB;
            pA.x = pk_bf16x2(vA.x, vA.y); pA.y = pk_residual(vA, pA.x);
            pB.x = pk_bf16x2(vB.x, vB.y); pB.y = pk_residual(vB, pB.x);
            pk_s[rows[half * 2] * PST + pidx] = pA;
            pk_s[rows[half * 2 + 1] * PST + pidx] = pB;
        }
    }
    __syncthreads();
}

// ---------------- LN(+affine)+ReLU for node kernels (stride LDH) ----------------
template <int ROWS>
__device__ __forceinline__ void ln_relu(float* hid_s, float* mu_s, float* rs_s,
                                        const float* __restrict__ gam,
                                        const float* __restrict__ bet) {
    const int t = threadIdx.x;
    const int w = t >> 5, lane = t & 31;
    __syncthreads();
    for (int e = w; e < ROWS; e += 4) {
        float s = 0.f, s2 = 0.f;
#pragma unroll
        for (int j = 0; j < 4; j++) {
            const float v = hid_s[e * LDH + lane + j * 32];
            s += v; s2 += v * v;
        }
#pragma unroll
        for (int o = 16; o; o >>= 1) {
            s  += __shfl_down_sync(0xffffffffu, s, o);
            s2 += __shfl_down_sync(0xffffffffu, s2, o);
        }
        if (lane == 0) {
            const float mu = s * (1.f / 128.f);
            const float var = s2 * (1.f / 128.f) - mu * mu;
            mu_s[e] = mu;
            rs_s[e] = rsqrtf(var + 1e-5f);
        }
    }
    __syncthreads();
    const float gt = gam[t], bt = bet[t];
#pragma unroll
    for (int e = 0; e < ROWS; e++) {
        float v = hid_s[e * LDH + t];
        v = fmaf((v - mu_s[e]) * rs_s[e], gt, bt);
        hid_s[e * LDH + t] = fmaxf(v, 0.f);
    }
    __syncthreads();
}

// ---------------- kernels ----------------
__global__ void init_kernel(int n) {
    const int i = blockIdx.x * blockDim.x + threadIdx.x;
    if (i < n * 128) g_attn[i] = 0.f;
    if (i < n * 16) { g_mx[i] = __int_as_float(0xff800000); g_den[i] = 0.f; }
}

__global__ void split_kernel(const float* qW1, const float* qW2,
                             const float* kW1, const float* kW2,
                             const float* vW1, const float* vW2,
                             const float* oW1, const float* oW2) {
    const int m = blockIdx.y;
    const float* src; int dst, K, Klim;
    switch (m) {
        case 0:  src = qW1;             dst = P_QW1;  K = 128; Klim = 128; break;
        case 1:  src = qW2;             dst = P_QW2;  K = 128; Klim = 128; break;
        case 2:  src = kW1 + 24 * 128;  dst = P_KW1D; K = 128; Klim = 128; break;
        case 3:  src = kW1 + 152 * 128; dst = P_KW1S; K = 128; Klim = 128; break;
        case 4:  src = vW1 + 24 * 128;  dst = P_VW1D; K = 128; Klim = 128; break;
        case 5:  src = vW1 + 152 * 128; dst = P_VW1S; K = 128; Klim = 128; break;
        case 6:  src = kW2;             dst = P_KW2;  K = 128; Klim = 128; break;
        case 7:  src = vW2;             dst = P_VW2;  K = 128; Klim = 128; break;
        case 8:  src = oW1;             dst = P_OW1;  K = 256; Klim = 256; break;
        case 9:  src = oW2;             dst = P_OW2;  K = 128; Klim = 128; break;
        case 10: src = kW1;             dst = P_KW1A; K = 32;  Klim = 24;  break;
        default: src = vW1;             dst = P_VW1A; K = 32;  Klim = 24;  break;
    }
    const int cnt = (K >> 4) * 128 * 4;
    for (int i = blockIdx.x * blockDim.x + threadIdx.x; i < cnt;
         i += gridDim.x * blockDim.x) {
        const int tig = i & 3;
        const int nc  = (i >> 2) & 127;
        const int k16 = i >> 9;
        const int r0 = k16 * 16 + 2 * tig;
        float2 x0, x1;
        x0.x = (r0     < Klim) ? src[(r0    ) * 128 + nc] : 0.f;
        x0.y = (r0 + 1 < Klim) ? src[(r0 + 1) * 128 + nc] : 0.f;
        x1.x = (r0 + 8 < Klim) ? src[(r0 + 8) * 128 + nc] : 0.f;
        x1.y = (r0 + 9 < Klim) ? src[(r0 + 9) * 128 + nc] : 0.f;
        uint4 b;
        b.x = pk_bf16x2(x0.x, x0.y);
        b.y = pk_bf16x2(x1.x, x1.y);
        b.z = pk_residual(x0, b.x);
        b.w = pk_residual(x1, b.y);
        g_wpk[dst + i] = b;
    }
}

__global__ void __launch_bounds__(NTHREADS)
nodeprep_kernel(const float* __restrict__ h, int n,
                const float* qb1, const float* qg, const float* qbe,
                const float* qb2) {
    __shared__ __align__(16) float in_s[TILE * LDH];
    __shared__ __align__(16) float hid_s[TILE * LDH];
    __shared__ float mu_s[TILE], rs_s[TILE];
    const int t = threadIdx.x;
    const int n0 = blockIdx.x * TILE;
    for (int e = 0; e < TILE; e++) in_s[e * LDH + t] = h[(n0 + e) * 128 + t];
    __syncthreads();

    mma_gemm16<128, LDH, true, false>(in_s, g_wpk + P_QW1, qb1, hid_s, 0);
    ln_relu<TILE>(hid_s, mu_s, rs_s, qg, qbe);
    mma_gemm16<128, LDH, true, true>(hid_s, g_wpk + P_QW2, qb2, g_q, n0);
    mma_gemm16<128, LDH, false, true>(in_s, g_wpk + P_KW1D, (const float*)0, g_kHd, n0);
    mma_gemm16<128, LDH, false, true>(in_s, g_wpk + P_KW1S, (const float*)0, g_kHs, n0);
    mma_gemm16<128, LDH, false, true>(in_s, g_wpk + P_VW1D, (const float*)0, g_vHd, n0);
    mma_gemm16<128, LDH, false, true>(in_s, g_wpk + P_VW1S, (const float*)0, g_vHs, n0);
}

// edge pass A (32 edges/block): frag-resident MLP; scores straight from fragments
__global__ void __launch_bounds__(NTHREADS)
edgeA_kernel(const float* __restrict__ rf, const float* __restrict__ ef,
             const int* __restrict__ srcI, const int* __restrict__ dstI, int Ecnt,
             const float* kb1, const float* kg, const float* kbe,
             const float* kb2) {
    __shared__ __align__(16) float sm_in[TE * LDE];
    __shared__ __align__(16) uint2 pk_s[TE * PST];
    __shared__ float2 wsum[TE * 4];
    __shared__ int dst_s[TE], src_s[TE];
    const int t = threadIdx.x;
    const int e0 = blockIdx.x * TE;
    const int ne = min(TE, Ecnt - e0);

    if (t < TE) {
        int idx = e0 + t; if (idx >= Ecnt) idx = Ecnt - 1;
        dst_s[t] = dstI[idx]; src_s[t] = srcI[idx];
    }
    for (int j = t; j < TE * 8; j += NTHREADS)
        sm_in[(j >> 3) * LDE + 24 + (j & 7)] = 0.f;
    for (int j = t; j < ne * 24; j += NTHREADS) {
        const int e = j / 24, i = j % 24;
        sm_in[e * LDE + i] = (i < 4) ? ef[(e0 + e) * 4 + i] : rf[(e0 + e) * 20 + (i - 4)];
    }
    __syncthreads();

    float c0[4][4], c1[4][4];
    mma_edge_l1_dual(sm_in, g_wpk + P_KW1A, kb1, g_kHd, g_kHs, dst_s, src_s, c0, c1);
    ln_frag_pack(c0, c1, wsum, pk_s, kg, kbe);
    mma_core_dual_pk<true>(pk_s, g_wpk + P_KW2, kb2, c0, c1);

    // score epilogue straight from fragments (both tiles)
    const int lane = t & 31, warp = t >> 5;
    const int g = lane >> 2, tig = lane & 3;
    const int n0 = warp * 32;
#pragma unroll
    for (int tt = 0; tt < 2; tt++) {
        const int r = tt * 16;
        float (*cc)[4] = tt ? c1 : c0;
#pragma unroll
        for (int nt = 0; nt < 4; nt++) {
            const int ce = n0 + nt * 8 + 2 * tig;
            const float2 qa = *(const float2*)(g_q + dst_s[r + g] * 128 + ce);
            const float2 qb = *(const float2*)(g_q + dst_s[r + g + 8] * 128 + ce);
            float p0 = cc[nt][0] * qa.x + cc[nt][1] * qa.y;
            float p8 = cc[nt][2] * qb.x + cc[nt][3] * qb.y;
            p0 += __shfl_xor_sync(0xffffffffu, p0, 1);
            p0 += __shfl_xor_sync(0xffffffffu, p0, 2);
            p8 += __shfl_xor_sync(0xffffffffu, p8, 1);
            p8 += __shfl_xor_sync(0xffffffffu, p8, 2);
            if (tig == 0) {
                const int hh = warp * 4 + nt;
                if (e0 + r + g < Ecnt) {
                    const float sc = p0 * 0.35355339059327373f; // 1/sqrt(8)
                    g_scores[(e0 + r + g) * 16 + hh] = sc;
                    atomicMaxF(&g_mx[dst_s[r + g] * 16 + hh], sc);
                }
                if (e0 + r + g + 8 < Ecnt) {
                    const float sc = p8 * 0.35355339059327373f;
                    g_scores[(e0 + r + g + 8) * 16 + hh] = sc;
                    atomicMaxF(&g_mx[dst_s[r + g + 8] * 16 + hh], sc);
                }
            }
        }
    }
}

__global__ void softmax_kernel(const int* __restrict__ dstI, int Ecnt) {
    const int gid = blockIdx.x * blockDim.x + threadIdx.x;
    if (gid >= Ecnt * 16) return;
    const int e = gid >> 4, hh = gid & 15;
    const int node = dstI[e];
    const float exv = expf(g_scores[gid] - g_mx[node * 16 + hh]);
    g_scores[gid] = exv;
    atomicAdd(&g_den[node * 16 + hh], exv);
}

// edge pass B (32 edges/block): frag-resident MLP; alpha*v scattered from fragments
__global__ void __launch_bounds__(NTHREADS)
edgeB_kernel(const float* __restrict__ rf, const float* __restrict__ ef,
             const float* __restrict__ ew,
             const int* __restrict__ srcI, const int* __restrict__ dstI, int Ecnt,
             const float* vb1, const float* vg, const float* vbe,
             const float* vb2) {
    __shared__ __align__(16) float sm_in[TE * LDE];
    __shared__ __align__(16) uint2 pk_s[TE * PST];
    __shared__ float2 wsum[TE * 4];
    __shared__ float ew_s[TE];
    __shared__ float alpha_s[TE * 16];
    __shared__ int dst_s[TE], src_s[TE];
    const int t = threadIdx.x;
    const int e0 = blockIdx.x * TE;
    const int ne = min(TE, Ecnt - e0);

    if (t < TE) {
        int idx = e0 + t; if (idx >= Ecnt) idx = Ecnt - 1;
        dst_s[t] = dstI[idx]; src_s[t] = srcI[idx];
        ew_s[t] = ew[idx];
    }
    for (int j = t; j < TE * 8; j += NTHREADS)
        sm_in[(j >> 3) * LDE + 24 + (j & 7)] = 0.f;
    for (int j = t; j < ne * 24; j += NTHREADS) {
        const int e = j / 24, i = j % 24;
        sm_in[e * LDE + i] = (i < 4) ? ef[(e0 + e) * 4 + i] : rf[(e0 + e) * 20 + (i - 4)];
    }
    __syncthreads();

    // alpha (incl. e_w); made visible by ln_frag_pack's barriers
    for (int j = t; j < ne * 16; j += NTHREADS) {
        const int e = j >> 4, hh = j & 15;
        alpha_s[j] = g_scores[(e0 + e) * 16 + hh] / g_den[dst_s[e] * 16 + hh] * ew_s[e];
    }

    float c0[4][4], c1[4][4];
    mma_edge_l1_dual(sm_in, g_wpk + P_VW1A, vb1, g_vHd, g_vHs, dst_s, src_s, c0, c1);
    ln_frag_pack(c0, c1, wsum, pk_s, vg, vbe);
    mma_core_dual_pk<true>(pk_s, g_wpk + P_VW2, vb2, c0, c1);

    // scatter epilogue straight from fragments (both tiles)
    const int lane = t & 31, warp = t >> 5;
    const int g = lane >> 2, tig = lane & 3;
    const int n0 = warp * 32;
#pragma unroll
    for (int tt = 0; tt < 2; tt++) {
        const int r = tt * 16;
        float (*cc)[4] = tt ? c1 : c0;
#pragma unroll
        for (int nt = 0; nt < 4; nt++) {
            const int hh = warp * 4 + nt;
            const int ce = n0 + nt * 8 + 2 * tig;
            if (e0 + r + g < Ecnt) {
                const float a = alpha_s[(r + g) * 16 + hh];
                red_add_v2(&g_attn[dst_s[r + g] * 128 + ce], cc[nt][0] * a, cc[nt][1] * a);
            }
            if (e0 + r + g + 8 < Ecnt) {
                const float a = alpha_s[(r + g + 8) * 16 + hh];
                red_add_v2(&g_attn[dst_s[r + g + 8] * 128 + ce], cc[nt][2] * a, cc[nt][3] * a);
            }
        }
    }
}

__global__ void __launch_bounds__(NTHREADS)
out_kernel(const float* __restrict__ h, float* __restrict__ outp, int n,
           const float* b1, const float* gam, const float* bet,
           const float* b2) {
    __shared__ __align__(16) float in_s[TILE * LDO];
    __shared__ __align__(16) float hid_s[TILE * LDH];
    __shared__ float mu_s[TILE], rs_s[TILE];
    const int t = threadIdx.x;
    const int n0 = blockIdx.x * TILE;
    for (int e = 0; e < TILE; e++) {
        const int node = n0 + e;
        in_s[e * LDO + t] = g_attn[node * 128 + t];
        in_s[e * LDO + 128 + t] = h[node * 128 + t];
    }
    __syncthreads();
    mma_gemm16<256, LDO, true, false>(in_s, g_wpk + P_OW1, b1, hid_s, 0);
    ln_relu<TILE>(hid_s, mu_s, rs_s, gam, bet);
    mma_gemm16<128, LDH, true, true>(hid_s, g_wpk + P_OW2, b2, outp, n0);
}

// ---------------- launch ----------------
extern "C" void kernel_launch(void* const* d_in, const int* in_sizes, int n_in,
                              void* d_out, int out_size) {
    int ih = -1, ir = -1, ief = -1, iei = -1, iew = -1, xk0 = -1;
    for (int i = 0; i < n_in; i++) {
        switch (in_sizes[i]) {
            case 6400000:  if (ih  < 0) ih  = i; break; // h [N,128]
            case 12000000: if (ir  < 0) ir  = i; break; // r_feat [E,20]
            case 2400000:  if (ief < 0) ief = i; break; // edge_feat [E,4]
            case 1200000:  if (iei < 0) iei = i; break; // edge_index [2,E]
            case 600000:   if (iew < 0) iew = i; break; // e_w [E]
            case 35840:    if (xk0 < 0) xk0 = i; break; // xk_W1 [280,128] (first)
            default: break;
        }
    }
    const int xv0 = xk0 + 6, xq0 = xk0 + 12, o0 = xk0 + 18;

    const float* h   = (const float*)d_in[ih];
    const float* rf  = (const float*)d_in[ir];
    const float* ef  = (const float*)d_in[ief];
    const float* ew  = (const float*)d_in[iew];
    const int*   ei  = (const int*)d_in[iei];
    const int N = in_sizes[ih] / 128;
    const int E = in_sizes[iew];
    const int* srcI = ei;
    const int* dstI = ei + E;

#define G(base, off) ((const float*)d_in[(base) + (off)])
    float* outp = (float*)d_out;

    init_kernel<<<(N * 128 + 255) / 256, 256>>>(N);
    {
        dim3 grid(32, 12);
        split_kernel<<<grid, 256>>>(G(xq0,0), G(xq0,4), G(xk0,0), G(xk0,4),
                                    G(xv0,0), G(xv0,4), G(o0,0),  G(o0,4));
    }
    nodeprep_kernel<<<(N + TILE - 1) / TILE, NTHREADS>>>(
        h, N, G(xq0,1), G(xq0,2), G(xq0,3), G(xq0,5));
    edgeA_kernel<<<(E + TE - 1) / TE, NTHREADS>>>(
        rf, ef, srcI, dstI, E,
        G(xk0,1), G(xk0,2), G(xk0,3), G(xk0,5));
    softmax_kernel<<<(E * 16 + 255) / 256, 256>>>(dstI, E);
    edgeB_kernel<<<(E + TE - 1) / TE, NTHREADS>>>(
        rf, ef, ew, srcI, dstI, E,
        G(xv0,1), G(xv0,2), G(xv0,3), G(xv0,5));
    out_kernel<<<(N + TILE - 1) / TILE, NTHREADS>>>(
        h, outp, N, G(o0,1), G(o0,2), G(o0,3), G(o0,5));
#undef G
}

// round 17
// speedup vs baseline: 1.1285x; 1.1285x over previous
#include <cuda_runtime.h>
#include <math.h>

#define TILE 16    // node kernels
#define TE 32      // edge kernels (two 16-row MMA tiles)
#define NTHREADS 128
#define NMAX 50000
#define EMAX 600000
#define LDH 136   // padded smem row stride for node kernels
#define LDO 264   // padded stride for 256-wide input tiles
#define LDE 40    // padded stride for 32-wide edge-feature tiles
#define PST 66    // uint2 stride for packed hidden state (64 pairs + pad)

// packed bf16 fragment arrays, offsets in uint4 units
#define P_QW1  0
#define P_QW2  4096
#define P_KW1D 8192
#define P_KW1S 12288
#define P_VW1D 16384
#define P_VW1S 20480
#define P_KW2  24576
#define P_VW2  28672
#define P_OW1  32768
#define P_OW2  40960
#define P_KW1A 45056   // kW1[0:24] zero-padded to K=32
#define P_VW1A 46080   // vW1[0:24] zero-padded to K=32
#define P_TOTAL 47104

// ---------------- device scratch (no allocations allowed) ----------------
// g_q/g_kHd/g_kHs/g_vHd/g_vHs use PERMUTED column layout:
//   original col c = n0 + nt*8 + 2*tig + b  stored at  p = n0 + tig*8 + nt*2 + b
// (fragment-gather friendly: each thread's 8 cols per row are contiguous 32B)
__device__ float g_q[NMAX * 128];
__device__ float g_kHd[NMAX * 128];
__device__ float g_kHs[NMAX * 128];
__device__ float g_vHd[NMAX * 128];
__device__ float g_vHs[NMAX * 128];
__device__ float g_attn[NMAX * 128];   // ORIGINAL layout (scatter target)
__device__ float g_mx[NMAX * 16];
__device__ float g_den[NMAX * 16];
__device__ float g_scores[EMAX * 16];
__device__ uint4 g_wpk[P_TOTAL];

// ---------------- bf16 helpers ----------------
__device__ __forceinline__ unsigned pk_bf16x2(float lo, float hi) {
    unsigned r;
    asm("cvt.rn.bf16x2.f32 %0, %1, %2;" : "=r"(r) : "f"(hi), "f"(lo));
    return r;
}
__device__ __forceinline__ unsigned pk_residual(float2 x, unsigned h) {
    const float hlo = __uint_as_float(h << 16);
    const float hhi = __uint_as_float(h & 0xFFFF0000u);
    return pk_bf16x2(x.x - hlo, x.y - hhi);
}

__device__ __forceinline__ void mma16(float (&c)[4], unsigned a0, unsigned a1,
                                      unsigned a2, unsigned a3,
                                      unsigned b0, unsigned b1) {
    asm("mma.sync.aligned.m16n8k16.row.col.f32.bf16.bf16.f32 "
        "{%0,%1,%2,%3}, {%4,%5,%6,%7}, {%8,%9}, {%0,%1,%2,%3};"
        : "+f"(c[0]), "+f"(c[1]), "+f"(c[2]), "+f"(c[3])
        : "r"(a0), "r"(a1), "r"(a2), "r"(a3), "r"(b0), "r"(b1));
}

// vector reduction: g_attn[ptr..ptr+1] += {x, y}  (sm_90+)
__device__ __forceinline__ void red_add_v2(float* ptr, float x, float y) {
    asm volatile("red.global.add.v2.f32 [%0], {%1, %2};"
                 :: "l"(ptr), "f"(x), "f"(y) : "memory");
}

// monotone float atomic max via signed/unsigned int tricks (init to -inf)
__device__ __forceinline__ void atomicMaxF(float* addr, float v) {
    if (v >= 0.f) atomicMax((int*)addr, __float_as_int(v));
    else          atomicMin((unsigned int*)addr, __float_as_uint(v));
}

// ---------------- A-fragment pack from fp32 smem ----------------
struct AFrag { unsigned ah0, ah1, ah2, ah3, al0, al1, al2, al3; };

template <int LDA>
__device__ __forceinline__ AFrag load_afrag(const float* __restrict__ A_s, int k,
                                            int g, int tig) {
    const float2 p0 = *(const float2*)(A_s + g * LDA + k + 2 * tig);
    const float2 p1 = *(const float2*)(A_s + (g + 8) * LDA + k + 2 * tig);
    const float2 p2 = *(const float2*)(A_s + g * LDA + k + 8 + 2 * tig);
    const float2 p3 = *(const float2*)(A_s + (g + 8) * LDA + k + 8 + 2 * tig);
    AFrag f;
    f.ah0 = pk_bf16x2(p0.x, p0.y); f.al0 = pk_residual(p0, f.ah0);
    f.ah1 = pk_bf16x2(p1.x, p1.y); f.al1 = pk_residual(p1, f.ah1);
    f.ah2 = pk_bf16x2(p2.x, p2.y); f.al2 = pk_residual(p2, f.ah2);
    f.ah3 = pk_bf16x2(p3.x, p3.y); f.al3 = pk_residual(p3, f.ah3);
    return f;
}

// A-fragment from pre-packed {hi,lo} uint2 smem (no conversions)
__device__ __forceinline__ AFrag load_apk(const uint2* __restrict__ pk,
                                          int row0, int kp, int tig) {
    const uint2 q0 = pk[row0 * PST + kp + tig];
    const uint2 q1 = pk[(row0 + 8) * PST + kp + tig];
    const uint2 q2 = pk[row0 * PST + kp + 4 + tig];
    const uint2 q3 = pk[(row0 + 8) * PST + kp + 4 + tig];
    AFrag f;
    f.ah0 = q0.x; f.al0 = q0.y;
    f.ah1 = q1.x; f.al1 = q1.y;
    f.ah2 = q2.x; f.al2 = q2.y;
    f.ah3 = q3.x; f.al3 = q3.y;
    return f;
}

__device__ __forceinline__ void mma3(float (&c)[4], const AFrag& f, const uint4& b) {
    mma16(c, f.ah0, f.ah1, f.ah2, f.ah3, b.x, b.y);
    mma16(c, f.al0, f.al1, f.al2, f.al3, b.x, b.y);
    mma16(c, f.ah0, f.ah1, f.ah2, f.ah3, b.z, b.w);
}

// ---------------- single-tile MMA core ----------------
template <int KIN, int LDA, bool BIAS>
__device__ __forceinline__ void mma_core(
    const float* __restrict__ A_s, const uint4* __restrict__ Bpk,
    const float* __restrict__ bias, float (&c)[4][4])
{
    const int lane = threadIdx.x & 31;
    const int warp = threadIdx.x >> 5;
    const int g = lane >> 2, tig = lane & 3;
    const int n0 = warp * 32;
#pragma unroll
    for (int nt = 0; nt < 4; nt++) {
        float be = 0.f, bo = 0.f;
        if (BIAS) {
            be = bias[n0 + nt * 8 + 2 * tig];
            bo = bias[n0 + nt * 8 + 2 * tig + 1];
        }
        c[nt][0] = be; c[nt][1] = bo; c[nt][2] = be; c[nt][3] = bo;
    }
#pragma unroll
    for (int k = 0; k < KIN; k += 16) {
        const AFrag f = load_afrag<LDA>(A_s, k, g, tig);
        const int kbase = (k >> 4) * 128;
#pragma unroll
        for (int nt = 0; nt < 4; nt++) {
            const int nc = n0 + nt * 8 + g;
            const uint4 b = Bpk[(kbase + nc) * 4 + tig];
            mma3(c[nt], f, b);
        }
    }
}

// dual-tile lin2 from packed hidden state: B loaded once, zero A conversions
template <bool BIAS>
__device__ __forceinline__ void mma_core_dual_pk(
    const uint2* __restrict__ pk_s, const uint4* __restrict__ Bpk,
    const float* __restrict__ bias, float (&c0)[4][4], float (&c1)[4][4])
{
    const int lane = threadIdx.x & 31;
    const int warp = threadIdx.x >> 5;
    const int g = lane >> 2, tig = lane & 3;
    const int n0 = warp * 32;
#pragma unroll
    for (int nt = 0; nt < 4; nt++) {
        float be = 0.f, bo = 0.f;
        if (BIAS) {
            be = bias[n0 + nt * 8 + 2 * tig];
            bo = bias[n0 + nt * 8 + 2 * tig + 1];
        }
        c0[nt][0] = be; c0[nt][1] = bo; c0[nt][2] = be; c0[nt][3] = bo;
        c1[nt][0] = be; c1[nt][1] = bo; c1[nt][2] = be; c1[nt][3] = bo;
    }
#pragma unroll
    for (int k = 0; k < 128; k += 16) {
        const int kp = k >> 1;
        const AFrag f0 = load_apk(pk_s, g, kp, tig);
        const AFrag f1 = load_apk(pk_s, 16 + g, kp, tig);
        const int kbase = (k >> 4) * 128;
#pragma unroll
        for (int nt = 0; nt < 4; nt++) {
            const int nc = n0 + nt * 8 + g;
            const uint4 b = Bpk[(kbase + nc) * 4 + tig];
            mma3(c0[nt], f0, b);
            mma3(c1[nt], f1, b);
        }
    }
}

// store fragments to smem (stride LDH) or ORIGINAL-layout global
template <bool GLOBAL>
__device__ __forceinline__ void frag_store(float (&c)[4][4], float* __restrict__ C,
                                           int row0) {
    const int lane = threadIdx.x & 31;
    const int warp = threadIdx.x >> 5;
    const int g = lane >> 2, tig = lane & 3;
    const int n0 = warp * 32;
#pragma unroll
    for (int nt = 0; nt < 4; nt++) {
        const int ce = n0 + nt * 8 + 2 * tig;
        if (GLOBAL) {
            C[(row0 + g) * 128 + ce]     = c[nt][0];
            C[(row0 + g) * 128 + ce + 1] = c[nt][1];
            C[(row0 + g + 8) * 128 + ce]     = c[nt][2];
            C[(row0 + g + 8) * 128 + ce + 1] = c[nt][3];
        } else {
            C[(row0 + g) * LDH + ce]     = c[nt][0];
            C[(row0 + g) * LDH + ce + 1] = c[nt][1];
            C[(row0 + g + 8) * LDH + ce]     = c[nt][2];
            C[(row0 + g + 8) * LDH + ce + 1] = c[nt][3];
        }
    }
}

// store fragments to PERMUTED-layout global: thread's 8 cols contiguous (2x STG.128)
__device__ __forceinline__ void frag_store_gperm(float (&c)[4][4],
                                                 float* __restrict__ C, int row0) {
    const int lane = threadIdx.x & 31;
    const int warp = threadIdx.x >> 5;
    const int g = lane >> 2, tig = lane & 3;
    const int base = warp * 32 + tig * 8;
    float4 w;
    w.x = c[0][0]; w.y = c[0][1]; w.z = c[1][0]; w.w = c[1][1];
    *(float4*)(C + (row0 + g) * 128 + base) = w;
    w.x = c[2][0]; w.y = c[2][1]; w.z = c[3][0]; w.w = c[3][1];
    *(float4*)(C + (row0 + g) * 128 + base + 4) = w;
    w.x = c[0][2]; w.y = c[0][3]; w.z = c[1][2]; w.w = c[1][3];
    *(float4*)(C + (row0 + g + 8) * 128 + base) = w;
    w.x = c[2][2]; w.y = c[2][3]; w.z = c[3][2]; w.w = c[3][3];
    *(float4*)(C + (row0 + g + 8) * 128 + base + 4) = w;
}

template <int KIN, int LDA, bool BIAS, bool GLOBAL>
__device__ __forceinline__ void mma_gemm16(
    const float* __restrict__ A_s, const uint4* __restrict__ Bpk,
    const float* __restrict__ bias, float* __restrict__ C, int row0)
{
    float c[4][4];
    mma_core<KIN, LDA, BIAS>(A_s, Bpk, bias, c);
    frag_store<GLOBAL>(c, C, row0);
}

// edge first layer (dual tile) -> fragments in registers; gathers from PERMUTED arrays
__device__ __forceinline__ void mma_edge_l1_dual(
    const float* __restrict__ A_s, const uint4* __restrict__ Bpk,
    const float* __restrict__ b1,
    const float* __restrict__ Hd, const float* __restrict__ Hs,
    const int* __restrict__ dst_s, const int* __restrict__ src_s,
    float (&c0)[4][4], float (&c1)[4][4])
{
    const int lane = threadIdx.x & 31;
    const int warp = threadIdx.x >> 5;
    const int g = lane >> 2, tig = lane & 3;
    const int n0 = warp * 32;
    const int base = n0 + tig * 8;

    float2 bd[4];
#pragma unroll
    for (int nt = 0; nt < 4; nt++)
        bd[nt] = *(const float2*)(b1 + n0 + nt * 8 + 2 * tig);

#pragma unroll
    for (int half = 0; half < 2; half++) {
        float (*cc)[4] = half ? c1 : c0;
        const int r0 = half * 16 + g, r8 = half * 16 + g + 8;
        const float* hd0 = Hd + dst_s[r0] * 128 + base;
        const float* hs0 = Hs + src_s[r0] * 128 + base;
        const float* hd8 = Hd + dst_s[r8] * 128 + base;
        const float* hs8 = Hs + src_s[r8] * 128 + base;
        const float4 da0 = *(const float4*)(hd0);
        const float4 da1 = *(const float4*)(hd0 + 4);
        const float4 sa0 = *(const float4*)(hs0);
        const float4 sa1 = *(const float4*)(hs0 + 4);
        const float4 db0 = *(const float4*)(hd8);
        const float4 db1 = *(const float4*)(hd8 + 4);
        const float4 sb0 = *(const float4*)(hs8);
        const float4 sb1 = *(const float4*)(hs8 + 4);
        cc[0][0] = bd[0].x + da0.x + sa0.x; cc[0][1] = bd[0].y + da0.y + sa0.y;
        cc[1][0] = bd[1].x + da0.z + sa0.z; cc[1][1] = bd[1].y + da0.w + sa0.w;
        cc[2][0] = bd[2].x + da1.x + sa1.x; cc[2][1] = bd[2].y + da1.y + sa1.y;
        cc[3][0] = bd[3].x + da1.z + sa1.z; cc[3][1] = bd[3].y + da1.w + sa1.w;
        cc[0][2] = bd[0].x + db0.x + sb0.x; cc[0][3] = bd[0].y + db0.y + sb0.y;
        cc[1][2] = bd[1].x + db0.z + sb0.z; cc[1][3] = bd[1].y + db0.w + sb0.w;
        cc[2][2] = bd[2].x + db1.x + sb1.x; cc[2][3] = bd[2].y + db1.y + sb1.y;
        cc[3][2] = bd[3].x + db1.z + sb1.z; cc[3][3] = bd[3].y + db1.w + sb1.w;
    }
#pragma unroll
    for (int k = 0; k < 32; k += 16) {
        const AFrag f0 = load_afrag<LDE>(A_s, k, g, tig);
        const AFrag f1 = load_afrag<LDE>(A_s + 16 * LDE, k, g, tig);
        const int kbase = (k >> 4) * 128;
#pragma unroll
        for (int nt = 0; nt < 4; nt++) {
            const int nc = n0 + nt * 8 + g;
            const uint4 b = Bpk[(kbase + nc) * 4 + tig];
            mma3(c0[nt], f0, b);
            mma3(c1[nt], f1, b);
        }
    }
}

// fragment-resident LayerNorm + ReLU + bf16 pack into pk_s ({hi,lo} per col pair)
__device__ __forceinline__ void ln_frag_pack(
    float (&c0)[4][4], float (&c1)[4][4],
    float2* __restrict__ wsum,   // [32 rows][4 warps]
    uint2* __restrict__ pk_s,
    const float* __restrict__ gam, const float* __restrict__ bet)
{
    const int lane = threadIdx.x & 31;
    const int warp = threadIdx.x >> 5;
    const int g = lane >> 2, tig = lane & 3;
    const int n0 = warp * 32;

    float s[4] = {0.f, 0.f, 0.f, 0.f}, s2[4] = {0.f, 0.f, 0.f, 0.f};
#pragma unroll
    for (int nt = 0; nt < 4; nt++) {
        s[0] += c0[nt][0] + c0[nt][1];
        s2[0] += c0[nt][0] * c0[nt][0] + c0[nt][1] * c0[nt][1];
        s[1] += c0[nt][2] + c0[nt][3];
        s2[1] += c0[nt][2] * c0[nt][2] + c0[nt][3] * c0[nt][3];
        s[2] += c1[nt][0] + c1[nt][1];
        s2[2] += c1[nt][0] * c1[nt][0] + c1[nt][1] * c1[nt][1];
        s[3] += c1[nt][2] + c1[nt][3];
        s2[3] += c1[nt][2] * c1[nt][2] + c1[nt][3] * c1[nt][3];
    }
#pragma unroll
    for (int r = 0; r < 4; r++) {
        s[r]  += __shfl_xor_sync(0xffffffffu, s[r], 1);
        s[r]  += __shfl_xor_sync(0xffffffffu, s[r], 2);
        s2[r] += __shfl_xor_sync(0xffffffffu, s2[r], 1);
        s2[r] += __shfl_xor_sync(0xffffffffu, s2[r], 2);
    }
    if (tig == 0) {
        wsum[g * 4 + warp]        = make_float2(s[0], s2[0]);
        wsum[(g + 8) * 4 + warp]  = make_float2(s[1], s2[1]);
        wsum[(16 + g) * 4 + warp] = make_float2(s[2], s2[2]);
        wsum[(24 + g) * 4 + warp] = make_float2(s[3], s2[3]);
    }
    __syncthreads();

    const int rows[4] = {g, g + 8, 16 + g, 24 + g};
    float mu[4], rs[4];
#pragma unroll
    for (int r = 0; r < 4; r++) {
        float ts = 0.f, ts2 = 0.f;
#pragma unroll
        for (int w = 0; w < 4; w++) {
            const float2 v = wsum[rows[r] * 4 + w];
            ts += v.x; ts2 += v.y;
        }
        const float m = ts * (1.f / 128.f);
        mu[r] = m;
        rs[r] = rsqrtf(ts2 * (1.f / 128.f) - m * m + 1e-5f);
    }

#pragma unroll
    for (int nt = 0; nt < 4; nt++) {
        const int ce = n0 + nt * 8 + 2 * tig;
        const float2 gm = *(const float2*)(gam + ce);
        const float2 bt = *(const float2*)(bet + ce);
        const int pidx = (n0 >> 1) + nt * 4 + tig;
#pragma unroll
        for (int half = 0; half < 2; half++) {
            float (*cc)[4] = half ? c1 : c0;
            const int rA = half * 2, rB = half * 2 + 1;
            float2 vA, vB;
            vA.x = fmaxf(fmaf((cc[nt][0] - mu[rA]) * rs[rA], gm.x, bt.x), 0.f);
            vA.y = fmaxf(fmaf((cc[nt][1] - mu[rA]) * rs[rA], gm.y, bt.y), 0.f);
            vB.x = fmaxf(fmaf((cc[nt][2] - mu[rB]) * rs[rB], gm.x, bt.x), 0.f);
            vB.y = fmaxf(fmaf((cc[nt][3] - mu[rB]) * rs[rB], gm.y, bt.y), 0.f);
            uint2 pA, pB;
            pA.x = pk_bf16x2(vA.x, vA.y); pA.y = pk_residual(vA, pA.x);
            pB.x = pk_bf16x2(vB.x, vB.y); pB.y = pk_residual(vB, pB.x);
            pk_s[rows[half * 2] * PST + pidx] = pA;
            pk_s[rows[half * 2 + 1] * PST + pidx] = pB;
        }
    }
    __syncthreads();
}

// ---------------- LN(+affine)+ReLU for node kernels (stride LDH) ----------------
template <int ROWS>
__device__ __forceinline__ void ln_relu(float* hid_s, float* mu_s, float* rs_s,
                                        const float* __restrict__ gam,
                                        const float* __restrict__ bet) {
    const int t = threadIdx.x;
    const int w = t >> 5, lane = t & 31;
    __syncthreads();
    for (int e = w; e < ROWS; e += 4) {
        float s = 0.f, s2 = 0.f;
#pragma unroll
        for (int j = 0; j < 4; j++) {
            const float v = hid_s[e * LDH + lane + j * 32];
            s += v; s2 += v * v;
        }
#pragma unroll
        for (int o = 16; o; o >>= 1) {
            s  += __shfl_down_sync(0xffffffffu, s, o);
            s2 += __shfl_down_sync(0xffffffffu, s2, o);
        }
        if (lane == 0) {
            const float mu = s * (1.f / 128.f);
            const float var = s2 * (1.f / 128.f) - mu * mu;
            mu_s[e] = mu;
            rs_s[e] = rsqrtf(var + 1e-5f);
        }
    }
    __syncthreads();
    const float gt = gam[t], bt = bet[t];
#pragma unroll
    for (int e = 0; e < ROWS; e++) {
        float v = hid_s[e * LDH + t];
        v = fmaf((v - mu_s[e]) * rs_s[e], gt, bt);
        hid_s[e * LDH + t] = fmaxf(v, 0.f);
    }
    __syncthreads();
}

// ---------------- kernels ----------------
__global__ void init_kernel(int n) {
    const int i = blockIdx.x * blockDim.x + threadIdx.x;
    if (i < n * 128) g_attn[i] = 0.f;
    if (i < n * 16) { g_mx[i] = __int_as_float(0xff800000); g_den[i] = 0.f; }
}

__global__ void split_kernel(const float* qW1, const float* qW2,
                             const float* kW1, const float* kW2,
                             const float* vW1, const float* vW2,
                             const float* oW1, const float* oW2) {
    const int m = blockIdx.y;
    const float* src; int dst, K, Klim;
    switch (m) {
        case 0:  src = qW1;             dst = P_QW1;  K = 128; Klim = 128; break;
        case 1:  src = qW2;             dst = P_QW2;  K = 128; Klim = 128; break;
        case 2:  src = kW1 + 24 * 128;  dst = P_KW1D; K = 128; Klim = 128; break;
        case 3:  src = kW1 + 152 * 128; dst = P_KW1S; K = 128; Klim = 128; break;
        case 4:  src = vW1 + 24 * 128;  dst = P_VW1D; K = 128; Klim = 128; break;
        case 5:  src = vW1 + 152 * 128; dst = P_VW1S; K = 128; Klim = 128; break;
        case 6:  src = kW2;             dst = P_KW2;  K = 128; Klim = 128; break;
        case 7:  src = vW2;             dst = P_VW2;  K = 128; Klim = 128; break;
        case 8:  src = oW1;             dst = P_OW1;  K = 256; Klim = 256; break;
        case 9:  src = oW2;             dst = P_OW2;  K = 128; Klim = 128; break;
        case 10: src = kW1;             dst = P_KW1A; K = 32;  Klim = 24;  break;
        default: src = vW1;             dst = P_VW1A; K = 32;  Klim = 24;  break;
    }
    const int cnt = (K >> 4) * 128 * 4;
    for (int i = blockIdx.x * blockDim.x + threadIdx.x; i < cnt;
         i += gridDim.x * blockDim.x) {
        const int tig = i & 3;
        const int nc  = (i >> 2) & 127;
        const int k16 = i >> 9;
        const int r0 = k16 * 16 + 2 * tig;
        float2 x0, x1;
        x0.x = (r0     < Klim) ? src[(r0    ) * 128 + nc] : 0.f;
        x0.y = (r0 + 1 < Klim) ? src[(r0 + 1) * 128 + nc] : 0.f;
        x1.x = (r0 + 8 < Klim) ? src[(r0 + 8) * 128 + nc] : 0.f;
        x1.y = (r0 + 9 < Klim) ? src[(r0 + 9) * 128 + nc] : 0.f;
        uint4 b;
        b.x = pk_bf16x2(x0.x, x0.y);
        b.y = pk_bf16x2(x1.x, x1.y);
        b.z = pk_residual(x0, b.x);
        b.w = pk_residual(x1, b.y);
        g_wpk[dst + i] = b;
    }
}

__global__ void __launch_bounds__(NTHREADS)
nodeprep_kernel(const float* __restrict__ h, int n,
                const float* qb1, const float* qg, const float* qbe,
                const float* qb2) {
    __shared__ __align__(16) float in_s[TILE * LDH];
    __shared__ __align__(16) float hid_s[TILE * LDH];
    __shared__ float mu_s[TILE], rs_s[TILE];
    const int t = threadIdx.x;
    const int n0 = blockIdx.x * TILE;
    for (int e = 0; e < TILE; e++) in_s[e * LDH + t] = h[(n0 + e) * 128 + t];
    __syncthreads();

    float c[4][4];
    mma_core<128, LDH, true>(in_s, g_wpk + P_QW1, qb1, c);
    frag_store<false>(c, hid_s, 0);
    ln_relu<TILE>(hid_s, mu_s, rs_s, qg, qbe);
    mma_core<128, LDH, true>(hid_s, g_wpk + P_QW2, qb2, c);
    frag_store_gperm(c, g_q, n0);
    mma_core<128, LDH, false>(in_s, g_wpk + P_KW1D, (const float*)0, c);
    frag_store_gperm(c, g_kHd, n0);
    mma_core<128, LDH, false>(in_s, g_wpk + P_KW1S, (const float*)0, c);
    frag_store_gperm(c, g_kHs, n0);
    mma_core<128, LDH, false>(in_s, g_wpk + P_VW1D, (const float*)0, c);
    frag_store_gperm(c, g_vHd, n0);
    mma_core<128, LDH, false>(in_s, g_wpk + P_VW1S, (const float*)0, c);
    frag_store_gperm(c, g_vHs, n0);
}

// edge pass A (32 edges/block): frag-resident MLP; scores straight from fragments
__global__ void __launch_bounds__(NTHREADS)
edgeA_kernel(const float* __restrict__ rf, const float* __restrict__ ef,
             const int* __restrict__ srcI, const int* __restrict__ dstI, int Ecnt,
             const float* kb1, const float* kg, const float* kbe,
             const float* kb2) {
    __shared__ __align__(16) float sm_in[TE * LDE];
    __shared__ __align__(16) uint2 pk_s[TE * PST];
    __shared__ float2 wsum[TE * 4];
    __shared__ int dst_s[TE], src_s[TE];
    const int t = threadIdx.x;
    const int e0 = blockIdx.x * TE;
    const int ne = min(TE, Ecnt - e0);

    if (t < TE) {
        int idx = e0 + t; if (idx >= Ecnt) idx = Ecnt - 1;
        dst_s[t] = dstI[idx]; src_s[t] = srcI[idx];
    }
    for (int j = t; j < TE * 8; j += NTHREADS)
        sm_in[(j >> 3) * LDE + 24 + (j & 7)] = 0.f;
    for (int j = t; j < ne * 24; j += NTHREADS) {
        const int e = j / 24, i = j % 24;
        sm_in[e * LDE + i] = (i < 4) ? ef[(e0 + e) * 4 + i] : rf[(e0 + e) * 20 + (i - 4)];
    }
    __syncthreads();

    float c0[4][4], c1[4][4];
    mma_edge_l1_dual(sm_in, g_wpk + P_KW1A, kb1, g_kHd, g_kHs, dst_s, src_s, c0, c1);
    ln_frag_pack(c0, c1, wsum, pk_s, kg, kbe);
    mma_core_dual_pk<true>(pk_s, g_wpk + P_KW2, kb2, c0, c1);

    // score epilogue straight from fragments; q gathered from permuted layout
    const int lane = t & 31, warp = t >> 5;
    const int g = lane >> 2, tig = lane & 3;
    const int base = warp * 32 + tig * 8;
#pragma unroll
    for (int tt = 0; tt < 2; tt++) {
        float (*cc)[4] = tt ? c1 : c0;
#pragma unroll
        for (int rr = 0; rr < 2; rr++) {
            const int row = tt * 16 + g + rr * 8;
            const float* qp = g_q + dst_s[row] * 128 + base;
            const float4 qa = *(const float4*)(qp);
            const float4 qb = *(const float4*)(qp + 4);
            const int ci = rr * 2;
            float p[4];
            p[0] = cc[0][ci] * qa.x + cc[0][ci + 1] * qa.y;
            p[1] = cc[1][ci] * qa.z + cc[1][ci + 1] * qa.w;
            p[2] = cc[2][ci] * qb.x + cc[2][ci + 1] * qb.y;
            p[3] = cc[3][ci] * qb.z + cc[3][ci + 1] * qb.w;
#pragma unroll
            for (int nt = 0; nt < 4; nt++) {
                p[nt] += __shfl_xor_sync(0xffffffffu, p[nt], 1);
                p[nt] += __shfl_xor_sync(0xffffffffu, p[nt], 2);
            }
            if (tig == 0 && e0 + row < Ecnt) {
#pragma unroll
                for (int nt = 0; nt < 4; nt++) {
                    const int hh = warp * 4 + nt;
                    const float sc = p[nt] * 0.35355339059327373f; // 1/sqrt(8)
                    g_scores[(e0 + row) * 16 + hh] = sc;
                    atomicMaxF(&g_mx[dst_s[row] * 16 + hh], sc);
                }
            }
        }
    }
}

__global__ void softmax_kernel(const int* __restrict__ dstI, int Ecnt) {
    const int gid = blockIdx.x * blockDim.x + threadIdx.x;
    if (gid >= Ecnt * 16) return;
    const int e = gid >> 4, hh = gid & 15;
    const int node = dstI[e];
    const float exv = expf(g_scores[gid] - g_mx[node * 16 + hh]);
    g_scores[gid] = exv;
    atomicAdd(&g_den[node * 16 + hh], exv);
}

// edge pass B (32 edges/block): frag-resident MLP; alpha*v scattered from fragments
__global__ void __launch_bounds__(NTHREADS)
edgeB_kernel(const float* __restrict__ rf, const float* __restrict__ ef,
             const float* __restrict__ ew,
             const int* __restrict__ srcI, const int* __restrict__ dstI, int Ecnt,
             const float* vb1, const float* vg, const float* vbe,
             const float* vb2) {
    __shared__ __align__(16) float sm_in[TE * LDE];
    __shared__ __align__(16) uint2 pk_s[TE * PST];
    __shared__ float2 wsum[TE * 4];
    __shared__ float ew_s[TE];
    __shared__ float alpha_s[TE * 16];
    __shared__ int dst_s[TE], src_s[TE];
    const int t = threadIdx.x;
    const int e0 = blockIdx.x * TE;
    const int ne = min(TE, Ecnt - e0);

    if (t < TE) {
        int idx = e0 + t; if (idx >= Ecnt) idx = Ecnt - 1;
        dst_s[t] = dstI[idx]; src_s[t] = srcI[idx];
        ew_s[t] = ew[idx];
    }
    for (int j = t; j < TE * 8; j += NTHREADS)
        sm_in[(j >> 3) * LDE + 24 + (j & 7)] = 0.f;
    for (int j = t; j < ne * 24; j += NTHREADS) {
        const int e = j / 24, i = j % 24;
        sm_in[e * LDE + i] = (i < 4) ? ef[(e0 + e) * 4 + i] : rf[(e0 + e) * 20 + (i - 4)];
    }
    __syncthreads();

    // alpha (incl. e_w); made visible by ln_frag_pack's barriers
    for (int j = t; j < ne * 16; j += NTHREADS) {
        const int e = j >> 4, hh = j & 15;
        alpha_s[j] = g_scores[(e0 + e) * 16 + hh] / g_den[dst_s[e] * 16 + hh] * ew_s[e];
    }

    float c0[4][4], c1[4][4];
    mma_edge_l1_dual(sm_in, g_wpk + P_VW1A, vb1, g_vHd, g_vHs, dst_s, src_s, c0, c1);
    ln_frag_pack(c0, c1, wsum, pk_s, vg, vbe);
    mma_core_dual_pk<true>(pk_s, g_wpk + P_VW2, vb2, c0, c1);

    // scatter epilogue straight from fragments (g_attn stays original layout)
    const int lane = t & 31, warp = t >> 5;
    const int g = lane >> 2, tig = lane & 3;
    const int n0 = warp * 32;
#pragma unroll
    for (int tt = 0; tt < 2; tt++) {
        const int r = tt * 16;
        float (*cc)[4] = tt ? c1 : c0;
#pragma unroll
        for (int nt = 0; nt < 4; nt++) {
            const int hh = warp * 4 + nt;
            const int ce = n0 + nt * 8 + 2 * tig;
            if (e0 + r + g < Ecnt) {
                const float a = alpha_s[(r + g) * 16 + hh];
                red_add_v2(&g_attn[dst_s[r + g] * 128 + ce], cc[nt][0] * a, cc[nt][1] * a);
            }
            if (e0 + r + g + 8 < Ecnt) {
                const float a = alpha_s[(r + g + 8) * 16 + hh];
                red_add_v2(&g_attn[dst_s[r + g + 8] * 128 + ce], cc[nt][2] * a, cc[nt][3] * a);
            }
        }
    }
}

__global__ void __launch_bounds__(NTHREADS)
out_kernel(const float* __restrict__ h, float* __restrict__ outp, int n,
           const float* b1, const float* gam, const float* bet,
           const float* b2) {
    __shared__ __align__(16) float in_s[TILE * LDO];
    __shared__ __align__(16) float hid_s[TILE * LDH];
    __shared__ float mu_s[TILE], rs_s[TILE];
    const int t = threadIdx.x;
    const int n0 = blockIdx.x * TILE;
    for (int e = 0; e < TILE; e++) {
        const int node = n0 + e;
        in_s[e * LDO + t] = g_attn[node * 128 + t];
        in_s[e * LDO + 128 + t] = h[node * 128 + t];
    }
    __syncthreads();
    mma_gemm16<256, LDO, true, false>(in_s, g_wpk + P_OW1, b1, hid_s, 0);
    ln_relu<TILE>(hid_s, mu_s, rs_s, gam, bet);
    mma_gemm16<128, LDH, true, true>(hid_s, g_wpk + P_OW2, b2, outp, n0);
}

// ---------------- launch ----------------
extern "C" void kernel_launch(void* const* d_in, const int* in_sizes, int n_in,
                              void* d_out, int out_size) {
    int ih = -1, ir = -1, ief = -1, iei = -1, iew = -1, xk0 = -1;
    for (int i = 0; i < n_in; i++) {
        switch (in_sizes[i]) {
            case 6400000:  if (ih  < 0) ih  = i; break; // h [N,128]
            case 12000000: if (ir  < 0) ir  = i; break; // r_feat [E,20]
            case 2400000:  if (ief < 0) ief = i; break; // edge_feat [E,4]
            case 1200000:  if (iei < 0) iei = i; break; // edge_index [2,E]
            case 600000:   if (iew < 0) iew = i; break; // e_w [E]
            case 35840:    if (xk0 < 0) xk0 = i; break; // xk_W1 [280,128] (first)
            default: break;
        }
    }
    const int xv0 = xk0 + 6, xq0 = xk0 + 12, o0 = xk0 + 18;

    const float* h   = (const float*)d_in[ih];
    const float* rf  = (const float*)d_in[ir];
    const float* ef  = (const float*)d_in[ief];
    const float* ew  = (const float*)d_in[iew];
    const int*   ei  = (const int*)d_in[iei];
    const int N = in_sizes[ih] / 128;
    const int E = in_sizes[iew];
    const int* srcI = ei;
    const int* dstI = ei + E;

#define G(base, off) ((const float*)d_in[(base) + (off)])
    float* outp = (float*)d_out;

    init_kernel<<<(N * 128 + 255) / 256, 256>>>(N);
    {
        dim3 grid(32, 12);
        split_kernel<<<grid, 256>>>(G(xq0,0), G(xq0,4), G(xk0,0), G(xk0,4),
                                    G(xv0,0), G(xv0,4), G(o0,0),  G(o0,4));
    }
    nodeprep_kernel<<<(N + TILE - 1) / TILE, NTHREADS>>>(
        h, N, G(xq0,1), G(xq0,2), G(xq0,3), G(xq0,5));
    edgeA_kernel<<<(E + TE - 1) / TE, NTHREADS>>>(
        rf, ef, srcI, dstI, E,
        G(xk0,1), G(xk0,2), G(xk0,3), G(xk0,5));
    softmax_kernel<<<(E * 16 + 255) / 256, 256>>>(dstI, E);
    edgeB_kernel<<<(E + TE - 1) / TE, NTHREADS>>>(
        rf, ef, ew, srcI, dstI, E,
        G(xv0,1), G(xv0,2), G(xv0,3), G(xv0,5));
    out_kernel<<<(N + TILE - 1) / TILE, NTHREADS>>>(
        h, outp, N, G(o0,1), G(o0,2), G(o0,3), G(o0,5));
#undef G
}